// round 1
// baseline (speedup 1.0000x reference)
#include <cuda_runtime.h>
#include <float.h>

// Problem constants (fixed shapes from reference setup_inputs)
#define BATCH 4
#define NQ 8192
#define NK 2048
#define CH 128
#define TPB 256        // threads per block == queries per block
#define QPB 256

__global__ __launch_bounds__(TPB, 1)
void fp_knn_interp_kernel(const float* __restrict__ xyz_q,
                          const float* __restrict__ xyz_k,
                          const float* __restrict__ v_k,
                          float* __restrict__ out)
{
    __shared__ float4 skey[NK];          // {x, y, z, ||k||^2}  -> 32 KB
    __shared__ int    sidx[QPB][3];
    __shared__ float  swgt[QPB][3];

    const int b   = blockIdx.y;
    const int q0  = blockIdx.x * QPB;
    const int tid = threadIdx.x;

    // ---- stage keys for this batch into shared memory ----
    const float* kb = xyz_k + (size_t)b * NK * 3;
    for (int j = tid; j < NK; j += TPB) {
        float kx = kb[j * 3 + 0];
        float ky = kb[j * 3 + 1];
        float kz = kb[j * 3 + 2];
        skey[j] = make_float4(kx, ky, kz, kx * kx + ky * ky + kz * kz);
    }
    __syncthreads();

    // ---- per-thread query: scan all keys, keep top-3 smallest ----
    const int q = q0 + tid;
    const float* qp = xyz_q + ((size_t)b * NQ + q) * 3;
    const float qx = qp[0], qy = qp[1], qz = qp[2];
    const float qq = qx * qx + qy * qy + qz * qz;

    // compare on s = ||k||^2 - 2 q.k  (ordering identical to full sq-dist)
    float d0 = FLT_MAX, d1 = FLT_MAX, d2 = FLT_MAX;
    int   i0 = 0, i1 = 0, i2 = 0;

    #pragma unroll 4
    for (int j = 0; j < NK; ++j) {
        float4 k = skey[j];                       // broadcast LDS.128
        float dot = fmaf(qx, k.x, fmaf(qy, k.y, qz * k.z));
        float s   = fmaf(-2.0f, dot, k.w);
        if (s < d2) {
            if (s < d1) {
                d2 = d1; i2 = i1;
                if (s < d0) { d1 = d0; i1 = i0; d0 = s; i0 = j; }
                else        { d1 = s;  i1 = j; }
            } else {
                d2 = s; i2 = j;
            }
        }
    }

    // ---- inverse-distance weights (add back ||q||^2, clamp, normalize) ----
    float e0 = fmaxf(d0 + qq, 1e-10f);
    float e1 = fmaxf(d1 + qq, 1e-10f);
    float e2 = fmaxf(d2 + qq, 1e-10f);
    float w0 = 1.0f / e0;
    float w1 = 1.0f / e1;
    float w2 = 1.0f / e2;
    float inv_sum = 1.0f / (w0 + w1 + w2);

    sidx[tid][0] = i0; sidx[tid][1] = i1; sidx[tid][2] = i2;
    swgt[tid][0] = w0 * inv_sum;
    swgt[tid][1] = w1 * inv_sum;
    swgt[tid][2] = w2 * inv_sum;
    __syncthreads();

    // ---- gather epilogue: one warp per query, lane = channel quad ----
    const float4* vb = (const float4*)(v_k + (size_t)b * NK * CH);
    float4* ob = (float4*)(out + ((size_t)b * NQ + q0) * CH);
    const int lane = tid & 31;
    const int warp = tid >> 5;

    #pragma unroll
    for (int ql = warp; ql < QPB; ql += TPB / 32) {
        int   j0 = sidx[ql][0], j1 = sidx[ql][1], j2 = sidx[ql][2];
        float a0 = swgt[ql][0], a1 = swgt[ql][1], a2 = swgt[ql][2];
        float4 va = vb[j0 * (CH / 4) + lane];
        float4 vc = vb[j1 * (CH / 4) + lane];
        float4 vd = vb[j2 * (CH / 4) + lane];
        float4 r;
        r.x = a0 * va.x + a1 * vc.x + a2 * vd.x;
        r.y = a0 * va.y + a1 * vc.y + a2 * vd.y;
        r.z = a0 * va.z + a1 * vc.z + a2 * vd.z;
        r.w = a0 * va.w + a1 * vc.w + a2 * vd.w;
        ob[ql * (CH / 4) + lane] = r;
    }
}

extern "C" void kernel_launch(void* const* d_in, const int* in_sizes, int n_in,
                              void* d_out, int out_size)
{
    const float* xyz_q = (const float*)d_in[0];   // [4, 8192, 3]
    const float* xyz_k = (const float*)d_in[1];   // [4, 2048, 3]
    const float* v_k   = (const float*)d_in[2];   // [4, 2048, 128]
    float* out = (float*)d_out;                   // [4, 8192, 128]

    dim3 grid(NQ / QPB, BATCH);   // (32, 4) = 128 CTAs
    fp_knn_interp_kernel<<<grid, TPB>>>(xyz_q, xyz_k, v_k, out);
}

// round 2
// speedup vs baseline: 1.4113x; 1.4113x over previous
#include <cuda_runtime.h>
#include <float.h>

// Fixed shapes from reference setup_inputs
#define BATCH 4
#define NQ 8192
#define NK 2048
#define CH 128
#define TPB 256
#define QPB 128          // queries per block (2 threads per query)
#define HALF_K (NK / 2)  // 1024 keys per thread

__device__ __forceinline__ void insert3(float s, int j,
                                        float& d0, float& d1, float& d2,
                                        int& i0, int& i1, int& i2)
{
    if (s < d2) {
        if (s < d1) {
            d2 = d1; i2 = i1;
            if (s < d0) { d1 = d0; i1 = i0; d0 = s; i0 = j; }
            else        { d1 = s;  i1 = j; }
        } else {
            d2 = s; i2 = j;
        }
    }
}

__global__ __launch_bounds__(TPB, 2)
void fp_knn_interp_kernel(const float* __restrict__ xyz_q,
                          const float* __restrict__ xyz_k,
                          const float* __restrict__ v_k,
                          float* __restrict__ out)
{
    __shared__ float4 skey[NK];          // {x, y, z, ||k||^2} -> 32 KB
    __shared__ int    sidx[QPB][3];
    __shared__ float  swgt[QPB][3];

    const int b   = blockIdx.y;
    const int q0  = blockIdx.x * QPB;
    const int tid = threadIdx.x;

    // ---- stage keys for this batch into shared memory ----
    const float* kb = xyz_k + (size_t)b * NK * 3;
    for (int j = tid; j < NK; j += TPB) {
        float kx = kb[j * 3 + 0];
        float ky = kb[j * 3 + 1];
        float kz = kb[j * 3 + 2];
        skey[j] = make_float4(kx, ky, kz, kx * kx + ky * ky + kz * kz);
    }
    __syncthreads();

    // ---- 2 threads per query: even lane scans keys [0,1024), odd [1024,2048) ----
    const int h = tid & 1;             // half id
    const int q = q0 + (tid >> 1);     // query handled by this thread pair
    const float* qp = xyz_q + ((size_t)b * NQ + q) * 3;
    const float qx = qp[0], qy = qp[1], qz = qp[2];
    const float qq  = fmaf(qx, qx, fmaf(qy, qy, qz * qz));
    const float qx2 = -2.0f * qx, qy2 = -2.0f * qy, qz2 = -2.0f * qz;

    // compare on s = ||k||^2 - 2 q.k (same ordering as full sq-dist)
    float d0 = FLT_MAX, d1 = FLT_MAX, d2 = FLT_MAX;
    int   i0 = 0, i1 = 0, i2 = 0;

    const float4* kbase = skey + h * HALF_K;
    #pragma unroll 4
    for (int j = 0; j < HALF_K; ++j) {
        float4 k = kbase[j];                      // LDS.128, 2 broadcast groups
        float s = fmaf(qx2, k.x, fmaf(qy2, k.y, fmaf(qz2, k.z, k.w)));
        insert3(s, j, d0, d1, d2, i0, i1, i2);
    }
    const int base = h * HALF_K;
    i0 += base; i1 += base; i2 += base;

    // ---- merge partner's top-3 via shfl (partner = lane ^ 1, same query) ----
    float e0 = __shfl_xor_sync(0xffffffffu, d0, 1);
    float e1 = __shfl_xor_sync(0xffffffffu, d1, 1);
    float e2 = __shfl_xor_sync(0xffffffffu, d2, 1);
    int   j0 = __shfl_xor_sync(0xffffffffu, i0, 1);
    int   j1 = __shfl_xor_sync(0xffffffffu, i1, 1);
    int   j2 = __shfl_xor_sync(0xffffffffu, i2, 1);
    insert3(e0, j0, d0, d1, d2, i0, i1, i2);
    insert3(e1, j1, d0, d1, d2, i0, i1, i2);
    insert3(e2, j2, d0, d1, d2, i0, i1, i2);

    // ---- even thread of each pair computes weights and publishes ----
    if (h == 0) {
        float w0 = 1.0f / fmaxf(d0 + qq, 1e-10f);
        float w1 = 1.0f / fmaxf(d1 + qq, 1e-10f);
        float w2 = 1.0f / fmaxf(d2 + qq, 1e-10f);
        float inv_sum = 1.0f / (w0 + w1 + w2);
        const int ql = tid >> 1;
        sidx[ql][0] = i0; sidx[ql][1] = i1; sidx[ql][2] = i2;
        swgt[ql][0] = w0 * inv_sum;
        swgt[ql][1] = w1 * inv_sum;
        swgt[ql][2] = w2 * inv_sum;
    }
    __syncthreads();

    // ---- gather epilogue: one warp per query, lane = channel quad ----
    const float4* vb = (const float4*)(v_k + (size_t)b * NK * CH);
    float4* ob = (float4*)(out + ((size_t)b * NQ + q0) * CH);
    const int lane = tid & 31;
    const int warp = tid >> 5;

    #pragma unroll
    for (int ql = warp; ql < QPB; ql += TPB / 32) {
        int   n0 = sidx[ql][0], n1 = sidx[ql][1], n2 = sidx[ql][2];
        float a0 = swgt[ql][0], a1 = swgt[ql][1], a2 = swgt[ql][2];
        float4 va = vb[n0 * (CH / 4) + lane];
        float4 vc = vb[n1 * (CH / 4) + lane];
        float4 vd = vb[n2 * (CH / 4) + lane];
        float4 r;
        r.x = a0 * va.x + a1 * vc.x + a2 * vd.x;
        r.y = a0 * va.y + a1 * vc.y + a2 * vd.y;
        r.z = a0 * va.z + a1 * vc.z + a2 * vd.z;
        r.w = a0 * va.w + a1 * vc.w + a2 * vd.w;
        ob[ql * (CH / 4) + lane] = r;
    }
}

extern "C" void kernel_launch(void* const* d_in, const int* in_sizes, int n_in,
                              void* d_out, int out_size)
{
    const float* xyz_q = (const float*)d_in[0];   // [4, 8192, 3]
    const float* xyz_k = (const float*)d_in[1];   // [4, 2048, 3]
    const float* v_k   = (const float*)d_in[2];   // [4, 2048, 128]
    float* out = (float*)d_out;                   // [4, 8192, 128]

    dim3 grid(NQ / QPB, BATCH);   // (64, 4) = 256 CTAs
    fp_knn_interp_kernel<<<grid, TPB>>>(xyz_q, xyz_k, v_k, out);
}